// round 10
// baseline (speedup 1.0000x reference)
#include <cuda_runtime.h>
#include <cuda_bf16.h>
#include <cstdint>

#define ROW_LEN 4096
#define THREADS 256          // two independent 128-thread row-groups
#define V4 8                 // 4096 floats / 4 per float4 / 128 threads

__global__ void __launch_bounds__(THREADS, 8)
quant_rowwise_split(const float* __restrict__ x, float* __restrict__ out)
{
    const int t     = threadIdx.x;
    const int group = t >> 7;          // 0: warps 0-3, 1: warps 4-7
    const int gt    = t & 127;         // thread id within group

    const size_t row  = (size_t)blockIdx.x * 2 + group;
    const size_t base = row * ROW_LEN;
    const float4* __restrict__ xr   = reinterpret_cast<const float4*>(x + base);
    float4* __restrict__       outr = reinterpret_cast<float4*>(out + base);

    // Front-batched vector loads: 8 consecutive independent LDG.128.cs (MLP_p1=8)
    float4 v[V4];
#pragma unroll
    for (int k = 0; k < V4; ++k)
        v[k] = __ldcs(&xr[gt + k * 128]);

    // Local min/max over 32 values, 2 independent chains
    float mn0 = v[0].x, mx0 = v[0].x;
    float mn1 = v[1].x, mx1 = v[1].x;
#pragma unroll
    for (int k = 0; k < V4; k += 2) {
        mn0 = fminf(mn0, fminf(fminf(v[k+0].x, v[k+0].y), fminf(v[k+0].z, v[k+0].w)));
        mx0 = fmaxf(mx0, fmaxf(fmaxf(v[k+0].x, v[k+0].y), fmaxf(v[k+0].z, v[k+0].w)));
        mn1 = fminf(mn1, fminf(fminf(v[k+1].x, v[k+1].y), fminf(v[k+1].z, v[k+1].w)));
        mx1 = fmaxf(mx1, fmaxf(fmaxf(v[k+1].x, v[k+1].y), fmaxf(v[k+1].z, v[k+1].w)));
    }
    float mn = fminf(mn0, mn1);
    float mx = fmaxf(mx0, mx1);

    // Warp reduce
#pragma unroll
    for (int off = 16; off > 0; off >>= 1) {
        mn = fminf(mn, __shfl_xor_sync(0xFFFFFFFFu, mn, off));
        mx = fmaxf(mx, __shfl_xor_sync(0xFFFFFFFFu, mx, off));
    }

    // Per-group reduce across 4 warps with a NAMED barrier scoped to the
    // 128 threads of this group — the two row-groups never couple.
    __shared__ float smn[2][4], smx[2][4];
    const int wig = (gt >> 5);         // warp index within group (0-3)
    const int lid = t & 31;
    if (lid == 0) { smn[group][wig] = mn; smx[group][wig] = mx; }
    asm volatile("bar.sync %0, 128;" :: "r"(group + 1) : "memory");

    float bmn = fminf(fminf(smn[group][0], smn[group][1]),
                      fminf(smn[group][2], smn[group][3]));
    float bmx = fmaxf(fmaxf(smx[group][0], smx[group][1]),
                      fmaxf(smx[group][2], smx[group][3]));

    float scale = (bmx - bmn) * (1.0f / 255.0f);
    scale = fminf(fmaxf(scale, 1e-5f), 1e4f);
    float zp = -bmn / scale;
    zp = fminf(fmaxf(zp, -1e4f), 1e4f);
    const float inv = 1.0f / scale;

    // Fake quant-dequant, streaming vector stores
#pragma unroll
    for (int k = 0; k < V4; ++k) {
        float4 r;
        float q;
        q = rintf(v[k].x * inv) + zp; q = fminf(fmaxf(q, 0.0f), 255.0f); r.x = (q - zp) * scale;
        q = rintf(v[k].y * inv) + zp; q = fminf(fmaxf(q, 0.0f), 255.0f); r.y = (q - zp) * scale;
        q = rintf(v[k].z * inv) + zp; q = fminf(fmaxf(q, 0.0f), 255.0f); r.z = (q - zp) * scale;
        q = rintf(v[k].w * inv) + zp; q = fminf(fmaxf(q, 0.0f), 255.0f); r.w = (q - zp) * scale;
        __stcs(&outr[gt + k * 128], r);
    }
}

extern "C" void kernel_launch(void* const* d_in, const int* in_sizes, int n_in,
                              void* d_out, int out_size)
{
    const float* x = (const float*)d_in[0];
    float* out = (float*)d_out;
    const int n_rows   = in_sizes[0] / ROW_LEN;   // 16384
    const int n_blocks = n_rows / 2;              // 8192
    quant_rowwise_split<<<n_blocks, THREADS>>>(x, out);
}

// round 11
// speedup vs baseline: 1.2303x; 1.2303x over previous
#include <cuda_runtime.h>
#include <cuda_bf16.h>
#include <cstdint>

#define ROW_LEN 4096
#define THREADS 256
#define V4 4   // 4096 floats / 4 per float4 / 256 threads

__global__ void __launch_bounds__(THREADS, 8)
quant_rowwise_kernel(const float* __restrict__ x, float* __restrict__ out)
{
    const size_t base = (size_t)blockIdx.x * ROW_LEN;
    const float4* __restrict__ xr   = reinterpret_cast<const float4*>(x + base);
    float4* __restrict__       outr = reinterpret_cast<float4*>(out + base);

    const int t = threadIdx.x;

    // Front-batched vector loads: 4 independent LDG.128.cs per thread.
    // 16 data regs + overhead fits the 32-reg / 8-CTA-per-SM envelope (no spill).
    float4 v[V4];
#pragma unroll
    for (int k = 0; k < V4; ++k)
        v[k] = __ldcs(&xr[t + k * THREADS]);

    // Local min/max over 16 values
    float mn = v[0].x, mx = v[0].x;
#pragma unroll
    for (int k = 0; k < V4; ++k) {
        mn = fminf(mn, fminf(fminf(v[k].x, v[k].y), fminf(v[k].z, v[k].w)));
        mx = fmaxf(mx, fmaxf(fmaxf(v[k].x, v[k].y), fmaxf(v[k].z, v[k].w)));
    }

    // Warp reduce
#pragma unroll
    for (int off = 16; off > 0; off >>= 1) {
        mn = fminf(mn, __shfl_xor_sync(0xFFFFFFFFu, mn, off));
        mx = fmaxf(mx, __shfl_xor_sync(0xFFFFFFFFu, mx, off));
    }

    // Block reduce: warp leaders publish, then EVERY thread folds the 8
    // partials and computes scale/zp redundantly — only ONE barrier total.
    __shared__ float smn[8], smx[8];
    const int wid = t >> 5;
    const int lid = t & 31;
    if (lid == 0) { smn[wid] = mn; smx[wid] = mx; }
    __syncthreads();

    float bmn = smn[0], bmx = smx[0];
#pragma unroll
    for (int i = 1; i < 8; ++i) {
        bmn = fminf(bmn, smn[i]);
        bmx = fmaxf(bmx, smx[i]);
    }
    float scale = (bmx - bmn) * (1.0f / 255.0f);
    scale = fminf(fmaxf(scale, 1e-5f), 1e4f);
    float zp = -bmn / scale;
    zp = fminf(fmaxf(zp, -1e4f), 1e4f);
    const float inv = 1.0f / scale;

    // Fake quant-dequant, streaming vector stores
#pragma unroll
    for (int k = 0; k < V4; ++k) {
        float4 r;
        float q;
        q = rintf(v[k].x * inv) + zp; q = fminf(fmaxf(q, 0.0f), 255.0f); r.x = (q - zp) * scale;
        q = rintf(v[k].y * inv) + zp; q = fminf(fmaxf(q, 0.0f), 255.0f); r.y = (q - zp) * scale;
        q = rintf(v[k].z * inv) + zp; q = fminf(fmaxf(q, 0.0f), 255.0f); r.z = (q - zp) * scale;
        q = rintf(v[k].w * inv) + zp; q = fminf(fmaxf(q, 0.0f), 255.0f); r.w = (q - zp) * scale;
        __stcs(&outr[t + k * THREADS], r);
    }
}

extern "C" void kernel_launch(void* const* d_in, const int* in_sizes, int n_in,
                              void* d_out, int out_size)
{
    const float* x = (const float*)d_in[0];
    float* out = (float*)d_out;
    const int n_rows = in_sizes[0] / ROW_LEN;   // 16384
    quant_rowwise_kernel<<<n_rows, THREADS>>>(x, out);
}